// round 15
// baseline (speedup 1.0000x reference)
#include <cuda_runtime.h>
#include <cuda_fp16.h>
#include <math.h>

#define SCALE_Q 0.17677669529663687f
#define KSTR 40   // attention smem row stride in halves
#define GS 72     // pipelined GEMM/adafm smem stride (144B rows, LDSM conflict-free)
#define FS 200    // single-shot GEMM smem stride (400B rows, LDSM conflict-free)

// ---------------- scratch (device globals) ----------------------------------
__device__ float g_x2v[25165824];            // x after attn residual (B,C,H,W)
__device__ __half g_a[25165824];             // activations fp16 (131072 x 192)
__device__ __half g_b[100663296];            // qkv (131072x576) then fc1 out (131072x768)
__device__ __half g_w[442368];               // weights fp16 (qkv|proj|fc1|fc2)
__device__ __half g_Mh[2][32][4096];         // per-batch conv matrices, [out][in], fp16
__device__ float2 g_gn[2][32][32];           // (mean, rstd)

__constant__ float c_cos8[8] = {
    1.f, 0.70710678118654752f, 0.f, -0.70710678118654752f,
   -1.f, -0.70710678118654752f, 0.f, 0.70710678118654752f};

// ---------------- helpers ----------------------------------------------------
__device__ __forceinline__ unsigned su32(const void* p) {
    return (unsigned)__cvta_generic_to_shared(p);
}
__device__ __forceinline__ void cpasync16(unsigned dst, const void* src) {
    asm volatile("cp.async.ca.shared.global [%0], [%1], 16;" :: "r"(dst), "l"(src) : "memory");
}
__device__ __forceinline__ void cpcommit() {
    asm volatile("cp.async.commit_group;" ::: "memory");
}
template <int W> __device__ __forceinline__ void cpwait() {
    asm volatile("cp.async.wait_group %0;" :: "n"(W) : "memory");
}
__device__ __forceinline__ void ldsm4(unsigned a, unsigned& r0, unsigned& r1,
                                      unsigned& r2, unsigned& r3) {
    asm volatile("ldmatrix.sync.aligned.m8n8.x4.shared.b16 {%0,%1,%2,%3}, [%4];"
                 : "=r"(r0), "=r"(r1), "=r"(r2), "=r"(r3) : "r"(a));
}
__device__ __forceinline__ void ldsm4t(unsigned a, unsigned& r0, unsigned& r1,
                                       unsigned& r2, unsigned& r3) {
    asm volatile("ldmatrix.sync.aligned.m8n8.x4.trans.shared.b16 {%0,%1,%2,%3}, [%4];"
                 : "=r"(r0), "=r"(r1), "=r"(r2), "=r"(r3) : "r"(a));
}
__device__ __forceinline__ void mma16816(float* c, const unsigned* a, const unsigned* b) {
    asm volatile(
        "mma.sync.aligned.m16n8k16.row.col.f32.f16.f16.f32 "
        "{%0,%1,%2,%3}, {%4,%5,%6,%7}, {%8,%9}, {%0,%1,%2,%3};"
        : "+f"(c[0]), "+f"(c[1]), "+f"(c[2]), "+f"(c[3])
        : "r"(a[0]), "r"(a[1]), "r"(a[2]), "r"(a[3]), "r"(b[0]), "r"(b[1]));
}
__device__ __forceinline__ unsigned packh2(float x, float y) {
    __half2 h = __floats2half2_rn(x, y);
    return *(unsigned*)&h;
}

// ---------------- K1: adaFM spectra -> per-batch conv matrices (fp16, [out][in])
__global__ void __launch_bounds__(256) k_prep(
    const float* __restrict__ t,
    const float* __restrict__ wmsa, const float* __restrict__ bmsa,
    const float* __restrict__ wmlp, const float* __restrict__ bmlp)
{
    int b = blockIdx.x, tid = threadIdx.x;
    __shared__ float st[640];
    __shared__ float s[2][40];
    __shared__ float seff[2][64];
    __shared__ float ker[2][64];

    for (int i = tid; i < 640; i += 256) {
        float v = t[b * 640 + i];
        st[i] = v / (1.f + __expf(-v));
    }
    __syncthreads();
    if (tid < 80) {
        int br = tid / 40, f = tid % 40;
        const float* w  = br ? wmlp : wmsa;
        const float* bb = br ? bmlp : bmsa;
        float acc = bb[f];
        for (int e = 0; e < 640; e++) acc = fmaf(st[e], w[f * 640 + e], acc);
        s[br][f] = acc;
    }
    __syncthreads();
    if (tid < 128) {
        int br = tid >> 6, i = tid & 63, k1 = i >> 3, k2 = i & 7;
        float v;
        if (k2 == 0 || k2 == 4)
            v = 0.5f * (s[br][k1 * 5 + k2] + s[br][((8 - k1) & 7) * 5 + k2]);
        else if (k2 < 4) v = s[br][k1 * 5 + k2];
        else             v = s[br][((8 - k1) & 7) * 5 + (8 - k2)];
        seff[br][i] = v;
    }
    __syncthreads();
    if (tid < 128) {
        int br = tid >> 6, i = tid & 63, d1 = i >> 3, d2 = i & 7;
        float acc = 0.f;
        #pragma unroll
        for (int k = 0; k < 64; k++)
            acc = fmaf(seff[br][k], c_cos8[((k >> 3) * d1 + (k & 7) * d2) & 7], acc);
        ker[br][i] = acc * (1.f / 64.f);
    }
    __syncthreads();
    for (int idx = tid; idx < 8192; idx += 256) {
        int br = idx >> 12, j = idx & 4095;
        int out = j >> 6, in = j & 63;
        g_Mh[br][b][j] = __float2half_rn(
            ker[br][(((out >> 3) - (in >> 3)) & 7) * 8 + (((out & 7) - (in & 7)) & 7)]);
    }
}

// ---------------- K1b: all weights fp32 -> fp16 (one launch) -----------------
__global__ void k_wconv4(const float* __restrict__ w0, const float* __restrict__ w1,
                         const float* __restrict__ w2, const float* __restrict__ w3,
                         __half* __restrict__ h)
{
    int i = blockIdx.x * 256 + threadIdx.x;
    const float* s; int off;
    if (i < 110592)      { s = w0; off = 0; }
    else if (i < 147456) { s = w1; off = 110592; }
    else if (i < 294912) { s = w2; off = 147456; }
    else if (i < 442368) { s = w3; off = 294912; }
    else return;
    h[i] = __float2half_rn(s[i - off]);
}

// ---------------- K2: GroupNorm stats ---------------------------------------
__global__ void __launch_bounds__(256) k_gnstats(const float* __restrict__ x, int gi)
{
    int g = blockIdx.x, b = blockIdx.y;
    const float* p = x + ((size_t)b * 192 + g * 6) * 4096;
    float s = 0.f, s2 = 0.f;
    for (int i = threadIdx.x; i < 24576; i += 256) {
        float v = p[i]; s += v; s2 = fmaf(v, v, s2);
    }
    #pragma unroll
    for (int o = 16; o; o >>= 1) {
        s += __shfl_xor_sync(~0u, s, o); s2 += __shfl_xor_sync(~0u, s2, o);
    }
    __shared__ float sh[2][8];
    int wid = threadIdx.x >> 5;
    if (!(threadIdx.x & 31)) { sh[0][wid] = s; sh[1][wid] = s2; }
    __syncthreads();
    if (threadIdx.x < 32) {
        s  = (threadIdx.x < 8) ? sh[0][threadIdx.x] : 0.f;
        s2 = (threadIdx.x < 8) ? sh[1][threadIdx.x] : 0.f;
        #pragma unroll
        for (int o = 4; o; o >>= 1) {
            s += __shfl_xor_sync(~0u, s, o); s2 += __shfl_xor_sync(~0u, s2, o);
        }
        if (!threadIdx.x) {
            float m = s * (1.f / 24576.f);
            float var = s2 * (1.f / 24576.f) - m * m;
            g_gn[gi][b][g] = make_float2(m, rsqrtf(var + 1e-5f));
        }
    }
}

// ---------------- K3: tensor-core GN+adafm: Y = M(64x64) @ X(64x192) --------
template <int MODE>
__global__ void __launch_bounds__(256) k_adafm_tc(
    const float* __restrict__ src,
    const float* __restrict__ gw, const float* __restrict__ gbv)
{
    __shared__ __half Xs[192 * GS];
    __shared__ __half Ms[64 * GS];
    __shared__ float ga[192], gb[192];

    int patch = blockIdx.x, b = blockIdx.y;
    int py = patch >> 3, px = patch & 7;
    int tid = threadIdx.x, lane = tid & 31, wid = tid >> 5;

    #pragma unroll
    for (int r = 0; r < 2; r++) {
        int e = tid * 2 + r;
        int row = e >> 3, ch = e & 7;
        cpasync16(su32(Ms + row * GS + ch * 8), &g_Mh[MODE][b][row * 64 + ch * 8]);
    }
    cpcommit();

    if (tid < 192) {
        float2 st = g_gn[MODE][b][tid / 6];
        float a = st.y * gw[tid];
        ga[tid] = a; gb[tid] = gbv[tid] - st.x * a;
    }
    __syncthreads();

    {
        const float* sb = src + ((size_t)b * 192) * 4096 + (py * 8) * 64 + px * 8;
        #pragma unroll
        for (int it = 0; it < 12; it++) {
            int idx = it * 256 + tid;
            int c = idx >> 4, q = idx & 15;
            float4 v = *(const float4*)(sb + (size_t)c * 4096 + (q >> 1) * 64 + (q & 1) * 4);
            float a = ga[c], o = gb[c];
            __half2* dst = (__half2*)(Xs + c * GS + q * 4);
            dst[0] = __floats2half2_rn(fmaf(v.x, a, o), fmaf(v.y, a, o));
            dst[1] = __floats2half2_rn(fmaf(v.z, a, o), fmaf(v.w, a, o));
        }
    }
    cpwait<0>();
    __syncthreads();

    int wr = (wid & 3) * 16, wc = (wid >> 2) * 96;
    float c[12][4];
    #pragma unroll
    for (int nt = 0; nt < 12; nt++)
        #pragma unroll
        for (int i = 0; i < 4; i++) c[nt][i] = 0.f;

    unsigned am[4][4];
    #pragma unroll
    for (int kk = 0; kk < 4; kk++) {
        int row = wr + (lane & 15);
        int col = kk * 16 + ((lane & 16) ? 8 : 0);
        ldsm4(su32(Ms) + (unsigned)((row * GS + col) * 2),
              am[kk][0], am[kk][1], am[kk][2], am[kk][3]);
    }
    #pragma unroll
    for (int kk = 0; kk < 4; kk++) {
        #pragma unroll
        for (int np = 0; np < 6; np++) {
            int row = wc + np * 16 + ((lane & 16) ? 8 : 0) + (lane & 7);
            int col = kk * 16 + ((lane & 8) ? 8 : 0);
            unsigned r0, r1, r2, r3;
            ldsm4(su32(Xs) + (unsigned)((row * GS + col) * 2), r0, r1, r2, r3);
            unsigned b0[2] = {r0, r1}, b1[2] = {r2, r3};
            mma16816(c[np * 2],     am[kk], b0);
            mma16816(c[np * 2 + 1], am[kk], b1);
        }
    }

    int g = lane >> 2, tg = lane & 3;
    #pragma unroll
    for (int h = 0; h < 2; h++) {
        int p = wr + g + h * 8;
        int hh = py * 8 + (p >> 3), ww = px * 8 + (p & 7);
        size_t off;
        if (MODE == 0) {
            int hh2 = (hh + 60) & 63, ww2 = (ww + 60) & 63;
            int win = ((hh2 >> 3) << 3) | (ww2 >> 3);
            int nn  = ((hh2 & 7) << 3) | (ww2 & 7);
            off = ((size_t)(b * 64 + win) * 64 + nn) * 192;
        } else {
            off = ((size_t)b * 4096 + hh * 64 + ww) * 192;
        }
        #pragma unroll
        for (int nt = 0; nt < 12; nt++) {
            int col = wc + nt * 8 + tg * 2;
            *(__half2*)(g_a + off + col) =
                __floats2half2_rn(c[nt][h * 2 + 0], c[nt][h * 2 + 1]);
        }
    }
}

// ---------------- K4a: single-shot GEMM for K=192 (one barrier total) --------
// EPI 0: +bias -> fp16 | 1: +bias GELU -> fp16 | 2: +bias win-rev+roll+res
template <int EPI>
__global__ void __launch_bounds__(256, 2) k_hgemm1s(
    const __half* __restrict__ A, const __half* __restrict__ W,
    const float* __restrict__ bias, float* __restrict__ Cf,
    __half* __restrict__ Ch,
    int N, const float* __restrict__ res)
{
    const int K = 192;
    extern __shared__ __half smem[];
    __half* As = smem;                 // 128 x FS
    __half* Bs = smem + 128 * FS;      // 96 x FS

    int m0 = blockIdx.y * 128, n0 = blockIdx.x * 96;
    int tid = threadIdx.x, lane = tid & 31, wid = tid >> 5;
    int wm = (wid & 3) * 32, wn = (wid >> 2) * 48;

    const __half* Ab = A + (size_t)m0 * K;
    const __half* Bb = W + (size_t)n0 * K;

    // fill whole-K tiles: A 3072 chunks (12/thread), B 2304 (9/thread)
    #pragma unroll
    for (int r = 0; r < 12; r++) {
        int e = tid + r * 256, row = e / 24, ch = e % 24;
        cpasync16(su32(As + row * FS + ch * 8), Ab + (size_t)row * K + ch * 8);
    }
    #pragma unroll
    for (int r = 0; r < 9; r++) {
        int e = tid + r * 256, row = e / 24, ch = e % 24;
        cpasync16(su32(Bs + row * FS + ch * 8), Bb + (size_t)row * K + ch * 8);
    }
    cpcommit();

    float c[2][6][4];
    #pragma unroll
    for (int mt = 0; mt < 2; mt++)
        #pragma unroll
        for (int nt = 0; nt < 6; nt++)
            #pragma unroll
            for (int i = 0; i < 4; i++) c[mt][nt][i] = 0.f;

    cpwait<0>();
    __syncthreads();

    unsigned sA = su32(As), sB = su32(Bs);
    #pragma unroll
    for (int kk = 0; kk < 12; kk++) {
        unsigned a[2][4];
        #pragma unroll
        for (int mt = 0; mt < 2; mt++) {
            int row = wm + mt * 16 + (lane & 15);
            int col = kk * 16 + ((lane & 16) ? 8 : 0);
            ldsm4(sA + (unsigned)((row * FS + col) * 2),
                  a[mt][0], a[mt][1], a[mt][2], a[mt][3]);
        }
        #pragma unroll
        for (int ntp = 0; ntp < 3; ntp++) {
            int row = wn + ntp * 16 + ((lane & 16) ? 8 : 0) + (lane & 7);
            int col = kk * 16 + ((lane & 8) ? 8 : 0);
            unsigned r0, r1, r2, r3;
            ldsm4(sB + (unsigned)((row * FS + col) * 2), r0, r1, r2, r3);
            unsigned b0[2] = {r0, r1}, b1[2] = {r2, r3};
            #pragma unroll
            for (int mt = 0; mt < 2; mt++) {
                mma16816(c[mt][ntp * 2],     a[mt], b0);
                mma16816(c[mt][ntp * 2 + 1], a[mt], b1);
            }
        }
    }

    int g = lane >> 2, tg = lane & 3;
    #pragma unroll
    for (int nt = 0; nt < 6; nt++) {
        int cb = n0 + wn + nt * 8 + tg * 2;
        float2 bv = *(const float2*)(bias + cb);
        #pragma unroll
        for (int mt = 0; mt < 2; mt++)
            #pragma unroll
            for (int h = 0; h < 2; h++) {
                int m = m0 + wm + mt * 16 + g + h * 8;
                float v0 = c[mt][nt][h * 2 + 0] + bv.x;
                float v1 = c[mt][nt][h * 2 + 1] + bv.y;
                if (EPI == 0) {
                    *(__half2*)(Ch + (size_t)m * N + cb) = __floats2half2_rn(v0, v1);
                } else if (EPI == 1) {
                    float g0 = 0.5f * v0 * (1.f + erff(v0 * 0.70710678118654752f));
                    float g1 = 0.5f * v1 * (1.f + erff(v1 * 0.70710678118654752f));
                    *(__half2*)(Ch + (size_t)m * N + cb) = __floats2half2_rn(g0, g1);
                } else {
                    int b = m >> 12, win = (m >> 6) & 63, nn = m & 63;
                    int hh = ((((win >> 3) << 3) + (nn >> 3)) + 4) & 63;
                    int ww = ((((win & 7) << 3) + (nn & 7)) + 4) & 63;
                    size_t base2 = ((size_t)b * 192) * 4096 + hh * 64 + ww;
                    size_t i0 = base2 + (size_t)cb * 4096;
                    size_t i1 = base2 + (size_t)(cb + 1) * 4096;
                    Cf[i0] = res[i0] + v0;
                    Cf[i1] = res[i1] + v1;
                }
            }
    }
}

// ---------------- K4b: pipelined GEMM (fc2, K=768), k-tile 64 ----------------
__global__ void __launch_bounds__(256, 2) k_hgemm_fc2(
    const __half* __restrict__ A, const __half* __restrict__ W,
    const float* __restrict__ bias, float* __restrict__ Cf,
    int K, int N, const float* __restrict__ res)
{
    extern __shared__ __half smem[];
    const int ASZ = 128 * GS, BSZ = 96 * GS;
    const int STG = ASZ + BSZ;

    int m0 = blockIdx.y * 128, n0 = blockIdx.x * 96;
    int tid = threadIdx.x, lane = tid & 31, wid = tid >> 5;
    int wm = (wid & 3) * 32, wn = (wid >> 2) * 48;

    const __half* Ab = A + (size_t)m0 * K;
    const __half* Bb = W + (size_t)n0 * K;
    int KT = K >> 6;

    float c[2][6][4];
    #pragma unroll
    for (int mt = 0; mt < 2; mt++)
        #pragma unroll
        for (int nt = 0; nt < 6; nt++)
            #pragma unroll
            for (int i = 0; i < 4; i++) c[mt][nt][i] = 0.f;

    auto fill = [&](int kt, int st) {
        __half* base = smem + st * STG;
        int k0 = kt * 64;
        #pragma unroll
        for (int r = 0; r < 4; r++) {
            int e = tid + r * 256, row = e >> 3, ch = e & 7;
            cpasync16(su32(base + row * GS + ch * 8),
                      Ab + (size_t)row * K + k0 + ch * 8);
        }
        #pragma unroll
        for (int r = 0; r < 3; r++) {
            int e = tid + r * 256, row = e >> 3, ch = e & 7;
            cpasync16(su32(base + ASZ + row * GS + ch * 8),
                      Bb + (size_t)row * K + k0 + ch * 8);
        }
        cpcommit();
    };

    fill(0, 0);
    for (int kt = 0; kt < KT; kt++) {
        if (kt + 1 < KT) { fill(kt + 1, (kt + 1) & 1); cpwait<1>(); }
        else             { cpwait<0>(); }
        __syncthreads();

        const __half* base = smem + (kt & 1) * STG;
        unsigned sA = su32(base);
        unsigned sB = su32(base + ASZ);

        #pragma unroll
        for (int kk = 0; kk < 4; kk++) {
            unsigned a[2][4];
            #pragma unroll
            for (int mt = 0; mt < 2; mt++) {
                int row = wm + mt * 16 + (lane & 15);
                int col = kk * 16 + ((lane & 16) ? 8 : 0);
                ldsm4(sA + (unsigned)((row * GS + col) * 2),
                      a[mt][0], a[mt][1], a[mt][2], a[mt][3]);
            }
            #pragma unroll
            for (int ntp = 0; ntp < 3; ntp++) {
                int row = wn + ntp * 16 + ((lane & 16) ? 8 : 0) + (lane & 7);
                int col = kk * 16 + ((lane & 8) ? 8 : 0);
                unsigned r0, r1, r2, r3;
                ldsm4(sB + (unsigned)((row * GS + col) * 2), r0, r1, r2, r3);
                unsigned b0[2] = {r0, r1}, b1[2] = {r2, r3};
                #pragma unroll
                for (int mt = 0; mt < 2; mt++) {
                    mma16816(c[mt][ntp * 2],     a[mt], b0);
                    mma16816(c[mt][ntp * 2 + 1], a[mt], b1);
                }
            }
        }
        __syncthreads();
    }

    int g = lane >> 2, tg = lane & 3;
    #pragma unroll
    for (int nt = 0; nt < 6; nt++) {
        int cb = n0 + wn + nt * 8 + tg * 2;
        float2 bv = *(const float2*)(bias + cb);
        #pragma unroll
        for (int mt = 0; mt < 2; mt++)
            #pragma unroll
            for (int h = 0; h < 2; h++) {
                int m = m0 + wm + mt * 16 + g + h * 8;
                float v0 = c[mt][nt][h * 2 + 0] + bv.x;
                float v1 = c[mt][nt][h * 2 + 1] + bv.y;
                int b = m >> 12, pix = m & 4095;
                size_t i0 = ((size_t)(b * 192 + cb)) * 4096 + pix;
                size_t i1 = i0 + 4096;
                Cf[i0] = res[i0] + v0;
                Cf[i1] = res[i1] + v1;
            }
    }
}

// ---------------- K5: tensor-core window attention ---------------------------
__global__ void __launch_bounds__(128) k_attn_tc(
    const __half* __restrict__ qkv, const float* __restrict__ rpb)
{
    __shared__ __half Qs[64 * KSTR], Ks[64 * KSTR], Vs[64 * KSTR];
    __shared__ float Br[225];
    __shared__ int Cat[64];

    int w = blockIdx.x, head = blockIdx.y;
    int tid = threadIdx.x, lane = tid & 31, wq = tid >> 5;

    const __half* base = qkv + (size_t)w * 64 * 576 + head * 32;
    #pragma unroll
    for (int r = 0; r < 2; r++) {
        int idx = tid + r * 128;
        int row = idx >> 2, ch = idx & 3;
        const __half* src = base + (size_t)row * 576 + ch * 8;
        unsigned doff = (unsigned)((row * KSTR + ch * 8) * 2);
        cpasync16(su32(Qs) + doff, src);
        cpasync16(su32(Ks) + doff, src + 192);
        cpasync16(su32(Vs) + doff, src + 384);
    }
    cpcommit();

    for (int i = tid; i < 225; i += 128) Br[i] = rpb[i * 6 + head];
    if (tid < 64) {
        int win = w & 63;
        int hh2 = ((win >> 3) << 3) + (tid >> 3);
        int ww2 = ((win & 7) << 3) + (tid & 7);
        int ch = hh2 < 56 ? 0 : (hh2 < 60 ? 1 : 2);
        int cw = ww2 < 56 ? 0 : (ww2 < 60 ? 1 : 2);
        Cat[tid] = ch * 3 + cw;
    }
    cpwait<0>();
    __syncthreads();

    int g = lane >> 2, tg = lane & 3;

    float c[8][4];
    #pragma unroll
    for (int nt = 0; nt < 8; nt++)
        #pragma unroll
        for (int i = 0; i < 4; i++) c[nt][i] = 0.f;

    unsigned aq[2][4];
    #pragma unroll
    for (int kk = 0; kk < 2; kk++) {
        int row = wq * 16 + (lane & 15);
        int col = kk * 16 + ((lane & 16) ? 8 : 0);
        ldsm4(su32(Qs) + (unsigned)((row * KSTR + col) * 2),
              aq[kk][0], aq[kk][1], aq[kk][2], aq[kk][3]);
    }
    #pragma unroll
    for (int kk = 0; kk < 2; kk++) {
        #pragma unroll
        for (int ntp = 0; ntp < 4; ntp++) {
            int row = ntp * 16 + ((lane & 16) ? 8 : 0) + (lane & 7);
            int col = kk * 16 + ((lane & 8) ? 8 : 0);
            unsigned r0, r1, r2, r3;
            ldsm4(su32(Ks) + (unsigned)((row * KSTR + col) * 2), r0, r1, r2, r3);
            unsigned b0[2] = {r0, r1}, b1[2] = {r2, r3};
            mma16816(c[ntp * 2],     aq[kk], b0);
            mma16816(c[ntp * 2 + 1], aq[kk], b1);
        }
    }

    int row0 = wq * 16 + g, row1 = row0 + 8;
    int rn0 = row0 >> 3, cn0 = row0 & 7, rn1 = row1 >> 3, cn1 = row1 & 7;
    int cat0 = Cat[row0], cat1 = Cat[row1];
    #pragma unroll
    for (int nt = 0; nt < 8; nt++) {
        #pragma unroll
        for (int j = 0; j < 2; j++) {
            int col = nt * 8 + tg * 2 + j;
            int rm = col >> 3, cm = col & 7, cc = Cat[col];
            float b0v = Br[(rn0 - rm + 7) * 15 + (cn0 - cm + 7)] + (cc != cat0 ? -100.f : 0.f);
            float b1v = Br[(rn1 - rm + 7) * 15 + (cn1 - cm + 7)] + (cc != cat1 ? -100.f : 0.f);
            c[nt][j]     = c[nt][j]     * SCALE_Q + b0v;
            c[nt][j + 2] = c[nt][j + 2] * SCALE_Q + b1v;
        }
    }

    float mx0 = -1e30f, mx1 = -1e30f;
    #pragma unroll
    for (int nt = 0; nt < 8; nt++) {
        mx0 = fmaxf(mx0, fmaxf(c[nt][0], c[nt][1]));
        mx1 = fmaxf(mx1, fmaxf(c[nt][2], c[nt][3]));
    }
    #pragma unroll
    for (int o = 1; o < 4; o <<= 1) {
        mx0 = fmaxf(mx0, __shfl_xor_sync(~0u, mx0, o));
        mx1 = fmaxf(mx1, __shfl_xor_sync(~0u, mx1, o));
    }
    float sm0 = 0.f, sm1 = 0.f;
    #pragma unroll
    for (int nt = 0; nt < 8; nt++) {
        c[nt][0] = __expf(c[nt][0] - mx0); sm0 += c[nt][0];
        c[nt][1] = __expf(c[nt][1] - mx0); sm0 += c[nt][1];
        c[nt][2] = __expf(c[nt][2] - mx1); sm1 += c[nt][2];
        c[nt][3] = __expf(c[nt][3] - mx1); sm1 += c[nt][3];
    }
    #pragma unroll
    for (int o = 1; o < 4; o <<= 1) {
        sm0 += __shfl_xor_sync(~0u, sm0, o);
        sm1 += __shfl_xor_sync(~0u, sm1, o);
    }
    float inv0 = 1.f / sm0, inv1 = 1.f / sm1;

    float c2[4][4];
    #pragma unroll
    for (int nt = 0; nt < 4; nt++)
        #pragma unroll
        for (int i = 0; i < 4; i++) c2[nt][i] = 0.f;

    #pragma unroll
    for (int kk = 0; kk < 4; kk++) {
        unsigned ap[4];
        ap[0] = packh2(c[kk * 2][0],     c[kk * 2][1]);
        ap[1] = packh2(c[kk * 2][2],     c[kk * 2][3]);
        ap[2] = packh2(c[kk * 2 + 1][0], c[kk * 2 + 1][1]);
        ap[3] = packh2(c[kk * 2 + 1][2], c[kk * 2 + 1][3]);
        #pragma unroll
        for (int np = 0; np < 2; np++) {
            int row = kk * 16 + (lane & 15);
            int col = np * 16 + ((lane & 16) ? 8 : 0);
            unsigned r0, r1, r2, r3;
            ldsm4t(su32(Vs) + (unsigned)((row * KSTR + col) * 2), r0, r1, r2, r3);
            unsigned b0[2] = {r0, r1}, b1[2] = {r2, r3};
            mma16816(c2[np * 2],     ap, b0);
            mma16816(c2[np * 2 + 1], ap, b1);
        }
    }

    size_t obase = ((size_t)w * 64) * 192 + head * 32;
    #pragma unroll
    for (int nt = 0; nt < 4; nt++) {
        int col = nt * 8 + tg * 2;
        *(__half2*)(g_a + obase + (size_t)row0 * 192 + col) =
            __floats2half2_rn(c2[nt][0] * inv0, c2[nt][1] * inv0);
        *(__half2*)(g_a + obase + (size_t)row1 * 192 + col) =
            __floats2half2_rn(c2[nt][2] * inv1, c2[nt][3] * inv1);
    }
}

// ---------------- launch ------------------------------------------------------
extern "C" void kernel_launch(void* const* d_in, const int* in_sizes, int n_in,
                              void* d_out, int out_size)
{
    const float* x    = (const float*)d_in[0];
    const float* t    = (const float*)d_in[1];
    const float* n1w  = (const float*)d_in[2];
    const float* n1b  = (const float*)d_in[3];
    const float* qkvw = (const float*)d_in[4];
    const float* qkvb = (const float*)d_in[5];
    const float* rpb  = (const float*)d_in[6];
    const float* pw   = (const float*)d_in[7];
    const float* pb   = (const float*)d_in[8];
    const float* n2w  = (const float*)d_in[9];
    const float* n2b  = (const float*)d_in[10];
    const float* f1w  = (const float*)d_in[11];
    const float* f1b  = (const float*)d_in[12];
    const float* f2w  = (const float*)d_in[13];
    const float* f2b  = (const float*)d_in[14];
    const float* amw  = (const float*)d_in[15];
    const float* amb  = (const float*)d_in[16];
    const float* alw  = (const float*)d_in[17];
    const float* alb  = (const float*)d_in[18];
    float* out = (float*)d_out;

    float *x2;
    __half *a16, *b16, *w16;
    cudaGetSymbolAddress((void**)&x2,  g_x2v);
    cudaGetSymbolAddress((void**)&a16, g_a);
    cudaGetSymbolAddress((void**)&b16, g_b);
    cudaGetSymbolAddress((void**)&w16, g_w);

    const int GEMM1S_SMEM = (128 * FS + 96 * FS) * 2;       // 89600 B
    const int GEMMP_SMEM  = 2 * (128 * GS + 96 * GS) * 2;   // 64512 B
    static int attr_done = 0;
    if (!attr_done) {
        cudaFuncSetAttribute(k_hgemm1s<0>, cudaFuncAttributeMaxDynamicSharedMemorySize, GEMM1S_SMEM);
        cudaFuncSetAttribute(k_hgemm1s<1>, cudaFuncAttributeMaxDynamicSharedMemorySize, GEMM1S_SMEM);
        cudaFuncSetAttribute(k_hgemm1s<2>, cudaFuncAttributeMaxDynamicSharedMemorySize, GEMM1S_SMEM);
        cudaFuncSetAttribute(k_hgemm_fc2, cudaFuncAttributeMaxDynamicSharedMemorySize, GEMMP_SMEM);
        attr_done = 1;
    }

    k_prep<<<32, 256>>>(t, amw, amb, alw, alb);
    k_wconv4<<<1728, 256>>>(qkvw, pw, f1w, f2w, w16);

    k_gnstats<<<dim3(32, 32), 256>>>(x, 0);
    k_adafm_tc<0><<<dim3(64, 32), 256>>>(x, n1w, n1b);
    // qkv: (131072 x 192) @ (576 x 192)^T -> fp16 into g_b
    k_hgemm1s<0><<<dim3(6, 1024), 256, GEMM1S_SMEM>>>(a16, w16, qkvb,
                                                      nullptr, b16, 576, nullptr);
    // tensor-core attention -> g_a (fp16)
    k_attn_tc<<<dim3(2048, 6), 128>>>(b16, rpb);
    // proj + window reverse + roll + residual -> x2
    k_hgemm1s<2><<<dim3(2, 1024), 256, GEMM1S_SMEM>>>(a16, w16 + 110592, pb,
                                                      x2, nullptr, 192, x);
    k_gnstats<<<dim3(32, 32), 256>>>(x2, 1);
    k_adafm_tc<1><<<dim3(64, 32), 256>>>(x2, n2w, n2b);
    // fc1 + GELU -> fp16
    k_hgemm1s<1><<<dim3(8, 1024), 256, GEMM1S_SMEM>>>(a16, w16 + 147456, f1b,
                                                      nullptr, b16, 768, nullptr);
    // fc2 + residual scatter -> out
    k_hgemm_fc2<<<dim3(2, 1024), 256, GEMMP_SMEM>>>(b16, w16 + 294912, f2b,
                                                    out, 768, 192, x2);
}

// round 16
// speedup vs baseline: 1.0336x; 1.0336x over previous
#include <cuda_runtime.h>
#include <cuda_fp16.h>
#include <math.h>

#define SCALE_Q 0.17677669529663687f
#define KSTR 40   // attention smem row stride in halves
#define GS 72     // GEMM/adafm smem stride (144B rows, LDSM conflict-free)

// ---------------- scratch (device globals) ----------------------------------
__device__ float g_x2v[25165824];            // x after attn residual (B,C,H,W)
__device__ __half g_a[25165824];             // activations fp16 (131072 x 192)
__device__ __half g_b[100663296];            // qkv (131072x576) then fc1 out (131072x768)
__device__ __half g_w[442368];               // weights fp16 (qkv|proj|fc1|fc2)
__device__ __half g_Mh[2][32][4096];         // per-batch conv matrices, [out][in], fp16
__device__ float2 g_gn[2][32][32];           // (mean, rstd)
__device__ float2 g_gs[32][32];              // fused GN2 stat accumulators (sum, sumsq)

__constant__ float c_cos8[8] = {
    1.f, 0.70710678118654752f, 0.f, -0.70710678118654752f,
   -1.f, -0.70710678118654752f, 0.f, 0.70710678118654752f};

// ---------------- helpers ----------------------------------------------------
__device__ __forceinline__ unsigned su32(const void* p) {
    return (unsigned)__cvta_generic_to_shared(p);
}
__device__ __forceinline__ void cpasync16(unsigned dst, const void* src) {
    asm volatile("cp.async.ca.shared.global [%0], [%1], 16;" :: "r"(dst), "l"(src) : "memory");
}
__device__ __forceinline__ void cpcommit() {
    asm volatile("cp.async.commit_group;" ::: "memory");
}
template <int W> __device__ __forceinline__ void cpwait() {
    asm volatile("cp.async.wait_group %0;" :: "n"(W) : "memory");
}
__device__ __forceinline__ void ldsm4(unsigned a, unsigned& r0, unsigned& r1,
                                      unsigned& r2, unsigned& r3) {
    asm volatile("ldmatrix.sync.aligned.m8n8.x4.shared.b16 {%0,%1,%2,%3}, [%4];"
                 : "=r"(r0), "=r"(r1), "=r"(r2), "=r"(r3) : "r"(a));
}
__device__ __forceinline__ void ldsm4t(unsigned a, unsigned& r0, unsigned& r1,
                                       unsigned& r2, unsigned& r3) {
    asm volatile("ldmatrix.sync.aligned.m8n8.x4.trans.shared.b16 {%0,%1,%2,%3}, [%4];"
                 : "=r"(r0), "=r"(r1), "=r"(r2), "=r"(r3) : "r"(a));
}
__device__ __forceinline__ void mma16816(float* c, const unsigned* a, const unsigned* b) {
    asm volatile(
        "mma.sync.aligned.m16n8k16.row.col.f32.f16.f16.f32 "
        "{%0,%1,%2,%3}, {%4,%5,%6,%7}, {%8,%9}, {%0,%1,%2,%3};"
        : "+f"(c[0]), "+f"(c[1]), "+f"(c[2]), "+f"(c[3])
        : "r"(a[0]), "r"(a[1]), "r"(a[2]), "r"(a[3]), "r"(b[0]), "r"(b[1]));
}
__device__ __forceinline__ unsigned packh2(float x, float y) {
    __half2 h = __floats2half2_rn(x, y);
    return *(unsigned*)&h;
}

// ---------------- K1: adaFM spectra -> per-batch conv matrices (fp16, [out][in])
__global__ void __launch_bounds__(256) k_prep(
    const float* __restrict__ t,
    const float* __restrict__ wmsa, const float* __restrict__ bmsa,
    const float* __restrict__ wmlp, const float* __restrict__ bmlp)
{
    int b = blockIdx.x, tid = threadIdx.x;
    __shared__ float st[640];
    __shared__ float s[2][40];
    __shared__ float seff[2][64];
    __shared__ float ker[2][64];

    for (int i = tid; i < 640; i += 256) {
        float v = t[b * 640 + i];
        st[i] = v / (1.f + __expf(-v));
    }
    __syncthreads();
    if (tid < 80) {
        int br = tid / 40, f = tid % 40;
        const float* w  = br ? wmlp : wmsa;
        const float* bb = br ? bmlp : bmsa;
        float acc = bb[f];
        for (int e = 0; e < 640; e++) acc = fmaf(st[e], w[f * 640 + e], acc);
        s[br][f] = acc;
    }
    __syncthreads();
    if (tid < 128) {
        int br = tid >> 6, i = tid & 63, k1 = i >> 3, k2 = i & 7;
        float v;
        if (k2 == 0 || k2 == 4)
            v = 0.5f * (s[br][k1 * 5 + k2] + s[br][((8 - k1) & 7) * 5 + k2]);
        else if (k2 < 4) v = s[br][k1 * 5 + k2];
        else             v = s[br][((8 - k1) & 7) * 5 + (8 - k2)];
        seff[br][i] = v;
    }
    __syncthreads();
    if (tid < 128) {
        int br = tid >> 6, i = tid & 63, d1 = i >> 3, d2 = i & 7;
        float acc = 0.f;
        #pragma unroll
        for (int k = 0; k < 64; k++)
            acc = fmaf(seff[br][k], c_cos8[((k >> 3) * d1 + (k & 7) * d2) & 7], acc);
        ker[br][i] = acc * (1.f / 64.f);
    }
    __syncthreads();
    for (int idx = tid; idx < 8192; idx += 256) {
        int br = idx >> 12, j = idx & 4095;
        int out = j >> 6, in = j & 63;
        g_Mh[br][b][j] = __float2half_rn(
            ker[br][(((out >> 3) - (in >> 3)) & 7) * 8 + (((out & 7) - (in & 7)) & 7)]);
    }
}

// ---------------- K1b: all weights fp32 -> fp16 (one launch) -----------------
__global__ void k_wconv4(const float* __restrict__ w0, const float* __restrict__ w1,
                         const float* __restrict__ w2, const float* __restrict__ w3,
                         __half* __restrict__ h)
{
    int i = blockIdx.x * 256 + threadIdx.x;
    const float* s; int off;
    if (i < 110592)      { s = w0; off = 0; }
    else if (i < 147456) { s = w1; off = 110592; }
    else if (i < 294912) { s = w2; off = 147456; }
    else if (i < 442368) { s = w3; off = 294912; }
    else return;
    h[i] = __float2half_rn(s[i - off]);
}

// ---------------- K2: GroupNorm stats (float4 loads) -------------------------
__global__ void __launch_bounds__(256) k_gnstats(const float* __restrict__ x, int gi)
{
    int g = blockIdx.x, b = blockIdx.y;
    const float4* p = (const float4*)(x + ((size_t)b * 192 + g * 6) * 4096);
    float s = 0.f, s2 = 0.f;
    for (int i = threadIdx.x; i < 6144; i += 256) {
        float4 v = p[i];
        s += v.x + v.y + v.z + v.w;
        s2 += v.x * v.x + v.y * v.y + v.z * v.z + v.w * v.w;
    }
    #pragma unroll
    for (int o = 16; o; o >>= 1) {
        s += __shfl_xor_sync(~0u, s, o); s2 += __shfl_xor_sync(~0u, s2, o);
    }
    __shared__ float sh[2][8];
    int wid = threadIdx.x >> 5;
    if (!(threadIdx.x & 31)) { sh[0][wid] = s; sh[1][wid] = s2; }
    __syncthreads();
    if (threadIdx.x < 32) {
        s  = (threadIdx.x < 8) ? sh[0][threadIdx.x] : 0.f;
        s2 = (threadIdx.x < 8) ? sh[1][threadIdx.x] : 0.f;
        #pragma unroll
        for (int o = 4; o; o >>= 1) {
            s += __shfl_xor_sync(~0u, s, o); s2 += __shfl_xor_sync(~0u, s2, o);
        }
        if (!threadIdx.x) {
            float m = s * (1.f / 24576.f);
            float var = s2 * (1.f / 24576.f) - m * m;
            g_gn[gi][b][g] = make_float2(m, rsqrtf(var + 1e-5f));
        }
    }
}

// ---------------- K2b: finalize fused GN2 stats -------------------------------
__global__ void k_gnfin()
{
    int i = threadIdx.x;            // 1024 threads
    int b = i >> 5, g = i & 31;
    float2 s = g_gs[b][g];
    float m = s.x * (1.f / 24576.f);
    float var = s.y * (1.f / 24576.f) - m * m;
    g_gn[1][b][g] = make_float2(m, rsqrtf(var + 1e-5f));
}

// ---------------- K3: tensor-core GN+adafm: Y = M(64x64) @ X(64x192) --------
template <int MODE>
__global__ void __launch_bounds__(256) k_adafm_tc(
    const float* __restrict__ src,
    const float* __restrict__ gw, const float* __restrict__ gbv)
{
    __shared__ __half Xs[192 * GS];
    __shared__ __half Ms[64 * GS];
    __shared__ float ga[192], gb[192];

    int patch = blockIdx.x, b = blockIdx.y;
    int py = patch >> 3, px = patch & 7;
    int tid = threadIdx.x, lane = tid & 31, wid = tid >> 5;

    #pragma unroll
    for (int r = 0; r < 2; r++) {
        int e = tid * 2 + r;
        int row = e >> 3, ch = e & 7;
        cpasync16(su32(Ms + row * GS + ch * 8), &g_Mh[MODE][b][row * 64 + ch * 8]);
    }
    cpcommit();

    if (tid < 192) {
        float2 st = g_gn[MODE][b][tid / 6];
        float a = st.y * gw[tid];
        ga[tid] = a; gb[tid] = gbv[tid] - st.x * a;
    }
    __syncthreads();

    {
        const float* sb = src + ((size_t)b * 192) * 4096 + (py * 8) * 64 + px * 8;
        #pragma unroll
        for (int it = 0; it < 12; it++) {
            int idx = it * 256 + tid;
            int c = idx >> 4, q = idx & 15;
            float4 v = *(const float4*)(sb + (size_t)c * 4096 + (q >> 1) * 64 + (q & 1) * 4);
            float a = ga[c], o = gb[c];
            __half2* dst = (__half2*)(Xs + c * GS + q * 4);
            dst[0] = __floats2half2_rn(fmaf(v.x, a, o), fmaf(v.y, a, o));
            dst[1] = __floats2half2_rn(fmaf(v.z, a, o), fmaf(v.w, a, o));
        }
    }
    cpwait<0>();
    __syncthreads();

    int wr = (wid & 3) * 16, wc = (wid >> 2) * 96;
    float c[12][4];
    #pragma unroll
    for (int nt = 0; nt < 12; nt++)
        #pragma unroll
        for (int i = 0; i < 4; i++) c[nt][i] = 0.f;

    unsigned am[4][4];
    #pragma unroll
    for (int kk = 0; kk < 4; kk++) {
        int row = wr + (lane & 15);
        int col = kk * 16 + ((lane & 16) ? 8 : 0);
        ldsm4(su32(Ms) + (unsigned)((row * GS + col) * 2),
              am[kk][0], am[kk][1], am[kk][2], am[kk][3]);
    }
    #pragma unroll
    for (int kk = 0; kk < 4; kk++) {
        #pragma unroll
        for (int np = 0; np < 6; np++) {
            int row = wc + np * 16 + ((lane & 16) ? 8 : 0) + (lane & 7);
            int col = kk * 16 + ((lane & 8) ? 8 : 0);
            unsigned r0, r1, r2, r3;
            ldsm4(su32(Xs) + (unsigned)((row * GS + col) * 2), r0, r1, r2, r3);
            unsigned b0[2] = {r0, r1}, b1[2] = {r2, r3};
            mma16816(c[np * 2],     am[kk], b0);
            mma16816(c[np * 2 + 1], am[kk], b1);
        }
    }

    int g = lane >> 2, tg = lane & 3;
    #pragma unroll
    for (int h = 0; h < 2; h++) {
        int p = wr + g + h * 8;
        int hh = py * 8 + (p >> 3), ww = px * 8 + (p & 7);
        size_t off;
        if (MODE == 0) {
            int hh2 = (hh + 60) & 63, ww2 = (ww + 60) & 63;
            int win = ((hh2 >> 3) << 3) | (ww2 >> 3);
            int nn  = ((hh2 & 7) << 3) | (ww2 & 7);
            off = ((size_t)(b * 64 + win) * 64 + nn) * 192;
        } else {
            off = ((size_t)b * 4096 + hh * 64 + ww) * 192;
        }
        #pragma unroll
        for (int nt = 0; nt < 12; nt++) {
            int col = wc + nt * 8 + tg * 2;
            *(__half2*)(g_a + off + col) =
                __floats2half2_rn(c[nt][h * 2 + 0], c[nt][h * 2 + 1]);
        }
    }
}

// ---------------- K4: pipelined fp16 tensor GEMM, block 128x96, k-tile 64 ---
// EPI 0: +bias -> fp16 | 1: +bias GELU -> fp16
// EPI 2: +bias win-rev+roll+res (+fused GN2 stats) | 3: +bias chan-major + res
template <int EPI>
__global__ void __launch_bounds__(256, 2) k_hgemm(
    const __half* __restrict__ A, const __half* __restrict__ W,
    const float* __restrict__ bias, float* __restrict__ Cf,
    __half* __restrict__ Ch,
    int K, int N, const float* __restrict__ res)
{
    extern __shared__ __half smem[];
    __shared__ float2 bsum[16];
    const int ASZ = 128 * GS, BSZ = 96 * GS;
    const int STG = ASZ + BSZ;

    int m0 = blockIdx.y * 128, n0 = blockIdx.x * 96;
    int tid = threadIdx.x, lane = tid & 31, wid = tid >> 5;
    int wm = (wid & 3) * 32, wn = (wid >> 2) * 48;

    const __half* Ab = A + (size_t)m0 * K;
    const __half* Bb = W + (size_t)n0 * K;
    int KT = K >> 6;

    float c[2][6][4];
    #pragma unroll
    for (int mt = 0; mt < 2; mt++)
        #pragma unroll
        for (int nt = 0; nt < 6; nt++)
            #pragma unroll
            for (int i = 0; i < 4; i++) c[mt][nt][i] = 0.f;

    if (EPI == 2 && tid < 16) bsum[tid] = make_float2(0.f, 0.f);

    auto fill = [&](int kt, int st) {
        __half* base = smem + st * STG;
        int k0 = kt * 64;
        #pragma unroll
        for (int r = 0; r < 4; r++) {
            int e = tid + r * 256, row = e >> 3, ch = e & 7;
            cpasync16(su32(base + row * GS + ch * 8),
                      Ab + (size_t)row * K + k0 + ch * 8);
        }
        #pragma unroll
        for (int r = 0; r < 3; r++) {
            int e = tid + r * 256, row = e >> 3, ch = e & 7;
            cpasync16(su32(base + ASZ + row * GS + ch * 8),
                      Bb + (size_t)row * K + k0 + ch * 8);
        }
        cpcommit();
    };

    fill(0, 0);
    for (int kt = 0; kt < KT; kt++) {
        if (kt + 1 < KT) { fill(kt + 1, (kt + 1) & 1); cpwait<1>(); }
        else             { cpwait<0>(); }
        __syncthreads();

        const __half* base = smem + (kt & 1) * STG;
        unsigned sA = su32(base);
        unsigned sB = su32(base + ASZ);

        #pragma unroll
        for (int kk = 0; kk < 4; kk++) {
            unsigned a[2][4];
            #pragma unroll
            for (int mt = 0; mt < 2; mt++) {
                int row = wm + mt * 16 + (lane & 15);
                int col = kk * 16 + ((lane & 16) ? 8 : 0);
                ldsm4(sA + (unsigned)((row * GS + col) * 2),
                      a[mt][0], a[mt][1], a[mt][2], a[mt][3]);
            }
            #pragma unroll
            for (int ntp = 0; ntp < 3; ntp++) {
                int row = wn + ntp * 16 + ((lane & 16) ? 8 : 0) + (lane & 7);
                int col = kk * 16 + ((lane & 8) ? 8 : 0);
                unsigned r0, r1, r2, r3;
                ldsm4(sB + (unsigned)((row * GS + col) * 2), r0, r1, r2, r3);
                unsigned b0[2] = {r0, r1}, b1[2] = {r2, r3};
                #pragma unroll
                for (int mt = 0; mt < 2; mt++) {
                    mma16816(c[mt][ntp * 2],     a[mt], b0);
                    mma16816(c[mt][ntp * 2 + 1], a[mt], b1);
                }
            }
        }
        __syncthreads();
    }

    int g = lane >> 2, tg = lane & 3;
    float lsum[6], lss[6];
    if (EPI == 2)
        #pragma unroll
        for (int nt = 0; nt < 6; nt++) { lsum[nt] = 0.f; lss[nt] = 0.f; }

    #pragma unroll
    for (int nt = 0; nt < 6; nt++) {
        int cb = n0 + wn + nt * 8 + tg * 2;
        float2 bv = *(const float2*)(bias + cb);
        #pragma unroll
        for (int mt = 0; mt < 2; mt++)
            #pragma unroll
            for (int h = 0; h < 2; h++) {
                int m = m0 + wm + mt * 16 + g + h * 8;
                float v0 = c[mt][nt][h * 2 + 0] + bv.x;
                float v1 = c[mt][nt][h * 2 + 1] + bv.y;
                if (EPI == 0) {
                    *(__half2*)(Ch + (size_t)m * N + cb) = __floats2half2_rn(v0, v1);
                } else if (EPI == 1) {
                    float g0 = 0.5f * v0 * (1.f + erff(v0 * 0.70710678118654752f));
                    float g1 = 0.5f * v1 * (1.f + erff(v1 * 0.70710678118654752f));
                    *(__half2*)(Ch + (size_t)m * N + cb) = __floats2half2_rn(g0, g1);
                } else if (EPI == 2) {
                    int b = m >> 12, win = (m >> 6) & 63, nn = m & 63;
                    int hh = ((((win >> 3) << 3) + (nn >> 3)) + 4) & 63;
                    int ww = ((((win & 7) << 3) + (nn & 7)) + 4) & 63;
                    size_t base2 = ((size_t)b * 192) * 4096 + hh * 64 + ww;
                    size_t i0 = base2 + (size_t)cb * 4096;
                    size_t i1 = base2 + (size_t)(cb + 1) * 4096;
                    float o0 = res[i0] + v0;
                    float o1 = res[i1] + v1;
                    Cf[i0] = o0;
                    Cf[i1] = o1;
                    lsum[nt] += o0 + o1;
                    lss[nt]  += o0 * o0 + o1 * o1;
                } else {
                    int b = m >> 12, pix = m & 4095;
                    size_t i0 = ((size_t)(b * 192 + cb)) * 4096 + pix;
                    size_t i1 = i0 + 4096;
                    Cf[i0] = res[i0] + v0;
                    Cf[i1] = res[i1] + v1;
                }
            }
    }

    if (EPI == 2) {
        __syncthreads();   // bsum zeroed before use (zero happened pre-mainloop)
        #pragma unroll
        for (int nt = 0; nt < 6; nt++) {
            float s = lsum[nt], ss = lss[nt];
            #pragma unroll
            for (int o = 4; o < 32; o <<= 1) {
                s  += __shfl_xor_sync(~0u, s,  o);
                ss += __shfl_xor_sync(~0u, ss, o);
            }
            if (lane < 4) {
                int cb = n0 + wn + nt * 8 + tg * 2;
                int lg = (cb - n0) / 6;
                atomicAdd(&bsum[lg].x, s);
                atomicAdd(&bsum[lg].y, ss);
            }
        }
        __syncthreads();
        if (tid < 16) {
            int b0 = m0 >> 12;
            int gg = n0 / 6 + tid;
            atomicAdd(&g_gs[b0][gg].x, bsum[tid].x);
            atomicAdd(&g_gs[b0][gg].y, bsum[tid].y);
        }
    }
}

// ---------------- K5: tensor-core window attention ---------------------------
__global__ void __launch_bounds__(128) k_attn_tc(
    const __half* __restrict__ qkv, const float* __restrict__ rpb)
{
    __shared__ __half Qs[64 * KSTR], Ks[64 * KSTR], Vs[64 * KSTR];
    __shared__ float Br[225];
    __shared__ int Cat[64];

    int w = blockIdx.x, head = blockIdx.y;
    int tid = threadIdx.x, lane = tid & 31, wq = tid >> 5;

    const __half* base = qkv + (size_t)w * 64 * 576 + head * 32;
    #pragma unroll
    for (int r = 0; r < 2; r++) {
        int idx = tid + r * 128;
        int row = idx >> 2, ch = idx & 3;
        const __half* src = base + (size_t)row * 576 + ch * 8;
        unsigned doff = (unsigned)((row * KSTR + ch * 8) * 2);
        cpasync16(su32(Qs) + doff, src);
        cpasync16(su32(Ks) + doff, src + 192);
        cpasync16(su32(Vs) + doff, src + 384);
    }
    cpcommit();

    for (int i = tid; i < 225; i += 128) Br[i] = rpb[i * 6 + head];
    if (tid < 64) {
        int win = w & 63;
        int hh2 = ((win >> 3) << 3) + (tid >> 3);
        int ww2 = ((win & 7) << 3) + (tid & 7);
        int ch = hh2 < 56 ? 0 : (hh2 < 60 ? 1 : 2);
        int cw = ww2 < 56 ? 0 : (ww2 < 60 ? 1 : 2);
        Cat[tid] = ch * 3 + cw;
    }
    cpwait<0>();
    __syncthreads();

    int g = lane >> 2, tg = lane & 3;

    float c[8][4];
    #pragma unroll
    for (int nt = 0; nt < 8; nt++)
        #pragma unroll
        for (int i = 0; i < 4; i++) c[nt][i] = 0.f;

    unsigned aq[2][4];
    #pragma unroll
    for (int kk = 0; kk < 2; kk++) {
        int row = wq * 16 + (lane & 15);
        int col = kk * 16 + ((lane & 16) ? 8 : 0);
        ldsm4(su32(Qs) + (unsigned)((row * KSTR + col) * 2),
              aq[kk][0], aq[kk][1], aq[kk][2], aq[kk][3]);
    }
    #pragma unroll
    for (int kk = 0; kk < 2; kk++) {
        #pragma unroll
        for (int ntp = 0; ntp < 4; ntp++) {
            int row = ntp * 16 + ((lane & 16) ? 8 : 0) + (lane & 7);
            int col = kk * 16 + ((lane & 8) ? 8 : 0);
            unsigned r0, r1, r2, r3;
            ldsm4(su32(Ks) + (unsigned)((row * KSTR + col) * 2), r0, r1, r2, r3);
            unsigned b0[2] = {r0, r1}, b1[2] = {r2, r3};
            mma16816(c[ntp * 2],     aq[kk], b0);
            mma16816(c[ntp * 2 + 1], aq[kk], b1);
        }
    }

    int row0 = wq * 16 + g, row1 = row0 + 8;
    int rn0 = row0 >> 3, cn0 = row0 & 7, rn1 = row1 >> 3, cn1 = row1 & 7;
    int cat0 = Cat[row0], cat1 = Cat[row1];
    #pragma unroll
    for (int nt = 0; nt < 8; nt++) {
        #pragma unroll
        for (int j = 0; j < 2; j++) {
            int col = nt * 8 + tg * 2 + j;
            int rm = col >> 3, cm = col & 7, cc = Cat[col];
            float b0v = Br[(rn0 - rm + 7) * 15 + (cn0 - cm + 7)] + (cc != cat0 ? -100.f : 0.f);
            float b1v = Br[(rn1 - rm + 7) * 15 + (cn1 - cm + 7)] + (cc != cat1 ? -100.f : 0.f);
            c[nt][j]     = c[nt][j]     * SCALE_Q + b0v;
            c[nt][j + 2] = c[nt][j + 2] * SCALE_Q + b1v;
        }
    }

    float mx0 = -1e30f, mx1 = -1e30f;
    #pragma unroll
    for (int nt = 0; nt < 8; nt++) {
        mx0 = fmaxf(mx0, fmaxf(c[nt][0], c[nt][1]));
        mx1 = fmaxf(mx1, fmaxf(c[nt][2], c[nt][3]));
    }
    #pragma unroll
    for (int o = 1; o < 4; o <<= 1) {
        mx0 = fmaxf(mx0, __shfl_xor_sync(~0u, mx0, o));
        mx1 = fmaxf(mx1, __shfl_xor_sync(~0u, mx1, o));
    }
    float sm0 = 0.f, sm1 = 0.f;
    #pragma unroll
    for (int nt = 0; nt < 8; nt++) {
        c[nt][0] = __expf(c[nt][0] - mx0); sm0 += c[nt][0];
        c[nt][1] = __expf(c[nt][1] - mx0); sm0 += c[nt][1];
        c[nt][2] = __expf(c[nt][2] - mx1); sm1 += c[nt][2];
        c[nt][3] = __expf(c[nt][3] - mx1); sm1 += c[nt][3];
    }
    #pragma unroll
    for (int o = 1; o < 4; o <<= 1) {
        sm0 += __shfl_xor_sync(~0u, sm0, o);
        sm1 += __shfl_xor_sync(~0u, sm1, o);
    }
    float inv0 = 1.f / sm0, inv1 = 1.f / sm1;

    float c2[4][4];
    #pragma unroll
    for (int nt = 0; nt < 4; nt++)
        #pragma unroll
        for (int i = 0; i < 4; i++) c2[nt][i] = 0.f;

    #pragma unroll
    for (int kk = 0; kk < 4; kk++) {
        unsigned ap[4];
        ap[0] = packh2(c[kk * 2][0],     c[kk * 2][1]);
        ap[1] = packh2(c[kk * 2][2],     c[kk * 2][3]);
        ap[2] = packh2(c[kk * 2 + 1][0], c[kk * 2 + 1][1]);
        ap[3] = packh2(c[kk * 2 + 1][2], c[kk * 2 + 1][3]);
        #pragma unroll
        for (int np = 0; np < 2; np++) {
            int row = kk * 16 + (lane & 15);
            int col = np * 16 + ((lane & 16) ? 8 : 0);
            unsigned r0, r1, r2, r3;
            ldsm4t(su32(Vs) + (unsigned)((row * KSTR + col) * 2), r0, r1, r2, r3);
            unsigned b0[2] = {r0, r1}, b1[2] = {r2, r3};
            mma16816(c2[np * 2],     ap, b0);
            mma16816(c2[np * 2 + 1], ap, b1);
        }
    }

    size_t obase = ((size_t)w * 64) * 192 + head * 32;
    #pragma unroll
    for (int nt = 0; nt < 4; nt++) {
        int col = nt * 8 + tg * 2;
        *(__half2*)(g_a + obase + (size_t)row0 * 192 + col) =
            __floats2half2_rn(c2[nt][0] * inv0, c2[nt][1] * inv0);
        *(__half2*)(g_a + obase + (size_t)row1 * 192 + col) =
            __floats2half2_rn(c2[nt][2] * inv1, c2[nt][3] * inv1);
    }
}

// ---------------- launch ------------------------------------------------------
extern "C" void kernel_launch(void* const* d_in, const int* in_sizes, int n_in,
                              void* d_out, int out_size)
{
    const float* x    = (const float*)d_in[0];
    const float* t    = (const float*)d_in[1];
    const float* n1w  = (const float*)d_in[2];
    const float* n1b  = (const float*)d_in[3];
    const float* qkvw = (const float*)d_in[4];
    const float* qkvb = (const float*)d_in[5];
    const float* rpb  = (const float*)d_in[6];
    const float* pw   = (const float*)d_in[7];
    const float* pb   = (const float*)d_in[8];
    const float* n2w  = (const float*)d_in[9];
    const float* n2b  = (const float*)d_in[10];
    const float* f1w  = (const float*)d_in[11];
    const float* f1b  = (const float*)d_in[12];
    const float* f2w  = (const float*)d_in[13];
    const float* f2b  = (const float*)d_in[14];
    const float* amw  = (const float*)d_in[15];
    const float* amb  = (const float*)d_in[16];
    const float* alw  = (const float*)d_in[17];
    const float* alb  = (const float*)d_in[18];
    float* out = (float*)d_out;

    float *x2;
    __half *a16, *b16, *w16;
    void* gs;
    cudaGetSymbolAddress((void**)&x2,  g_x2v);
    cudaGetSymbolAddress((void**)&a16, g_a);
    cudaGetSymbolAddress((void**)&b16, g_b);
    cudaGetSymbolAddress((void**)&w16, g_w);
    cudaGetSymbolAddress(&gs, g_gs);

    const int GEMM_SMEM = 2 * (128 * GS + 96 * GS) * 2;  // 64512 B
    static int attr_done = 0;
    if (!attr_done) {
        cudaFuncSetAttribute(k_hgemm<0>, cudaFuncAttributeMaxDynamicSharedMemorySize, GEMM_SMEM);
        cudaFuncSetAttribute(k_hgemm<1>, cudaFuncAttributeMaxDynamicSharedMemorySize, GEMM_SMEM);
        cudaFuncSetAttribute(k_hgemm<2>, cudaFuncAttributeMaxDynamicSharedMemorySize, GEMM_SMEM);
        cudaFuncSetAttribute(k_hgemm<3>, cudaFuncAttributeMaxDynamicSharedMemorySize, GEMM_SMEM);
        attr_done = 1;
    }

    k_prep<<<32, 256>>>(t, amw, amb, alw, alb);
    k_wconv4<<<1728, 256>>>(qkvw, pw, f1w, f2w, w16);
    cudaMemsetAsync(gs, 0, 32 * 32 * sizeof(float2));

    k_gnstats<<<dim3(32, 32), 256>>>(x, 0);
    k_adafm_tc<0><<<dim3(64, 32), 256>>>(x, n1w, n1b);
    // qkv: (131072 x 192) @ (576 x 192)^T -> fp16 into g_b
    k_hgemm<0><<<dim3(6, 1024), 256, GEMM_SMEM>>>(a16, w16, qkvb,
                                                  nullptr, b16, 192, 576, nullptr);
    // tensor-core attention -> g_a (fp16)
    k_attn_tc<<<dim3(2048, 6), 128>>>(b16, rpb);
    // proj + window reverse + roll + residual -> x2 (+ fused GN2 stats)
    k_hgemm<2><<<dim3(2, 1024), 256, GEMM_SMEM>>>(a16, w16 + 110592, pb,
                                                  x2, nullptr, 192, 192, x);
    k_gnfin<<<1, 1024>>>();
    k_adafm_tc<1><<<dim3(64, 32), 256>>>(x2, n2w, n2b);
    // fc1 + GELU -> fp16
    k_hgemm<1><<<dim3(8, 1024), 256, GEMM_SMEM>>>(a16, w16 + 147456, f1b,
                                                  nullptr, b16, 192, 768, nullptr);
    // fc2 + residual scatter -> out
    k_hgemm<3><<<dim3(2, 1024), 256, GEMM_SMEM>>>(b16, w16 + 294912, f2b,
                                                  out, nullptr, 768, 192, x2);
}